// round 8
// baseline (speedup 1.0000x reference)
#include <cuda_runtime.h>
#include <cuda_bf16.h>
#include <cstdint>

#define NN 50000
#define EE 800000
#define DD 128
#define HH 8

// ---------------- scratch (static device arrays; no allocation) ------------
__device__ float g_QKV[(size_t)NN * 384];
__device__ float g_P [(size_t)EE * DD];      // proj_e
__device__ float g_wV[(size_t)NN * DD];
__device__ float g_z [(size_t)NN * HH];
__device__ float g_bqkv[384];

// pre-split weights: bf16 hi/lo, [n][k] layout, packed in one buffer
#define OF_QKV  0                      // 384 x 128
#define OF_WE   49152                  // 128 x 128
#define OF_WON  65536
#define OF_WOE  81920
#define OF_W1N  98304                  // 256 x 128
#define OF_W2N  131072                 // 128 x 256
#define OF_W1E  163840
#define OF_W2E  196608
#define W_TOT   229376
__device__ __nv_bfloat16 g_WH[W_TOT];
__device__ __nv_bfloat16 g_WL[W_TOT];

// =================== helpers ===============================================
__device__ __forceinline__ void mma_bf16(float *c, const uint32_t *a,
                                         const uint32_t *b) {
    asm volatile(
        "mma.sync.aligned.m16n8k16.row.col.f32.bf16.bf16.f32 "
        "{%0,%1,%2,%3}, {%4,%5,%6,%7}, {%8,%9}, {%0,%1,%2,%3};"
        : "+f"(c[0]), "+f"(c[1]), "+f"(c[2]), "+f"(c[3])
        : "r"(a[0]), "r"(a[1]), "r"(a[2]), "r"(a[3]), "r"(b[0]), "r"(b[1]));
}
__device__ __forceinline__ void ldsm4(uint32_t *r, uint32_t addr) {
    asm volatile("ldmatrix.sync.aligned.m8n8.x4.shared.b16 {%0,%1,%2,%3}, [%4];"
                 : "=r"(r[0]), "=r"(r[1]), "=r"(r[2]), "=r"(r[3]) : "r"(addr));
}
__device__ __forceinline__ uint32_t pack_bf2(float x, float y) {
    __nv_bfloat162 t = __floats2bfloat162_rn(x, y);
    return *reinterpret_cast<uint32_t *>(&t);
}
__device__ __forceinline__ void split2(float x, float y, uint32_t &h, uint32_t &l) {
    __nv_bfloat16 hx = __float2bfloat16(x);
    __nv_bfloat16 hy = __float2bfloat16(y);
    float lx = x - __bfloat162float(hx);
    float ly = y - __bfloat162float(hy);
    __nv_bfloat162 hp; hp.x = hx; hp.y = hy;
    h = *reinterpret_cast<uint32_t *>(&hp);
    l = pack_bf2(lx, ly);
}
__device__ __forceinline__ void cp16(uint32_t saddr, const void *g) {
    asm volatile("cp.async.cg.shared.global [%0], [%1], 16;"
                 :: "r"(saddr), "l"(g));
}
#define CP_COMMIT() asm volatile("cp.async.commit_group;" ::: "memory")
#define CP_WAIT(n)  asm volatile("cp.async.wait_group %0;" :: "n"(n) : "memory")
#define CLIP5(x) fminf(fmaxf((x), -5.f), 5.f)

// A-style smem stride (bf16), W-buffer stride (bf16, 64-k tiles)
#define SSTR 136
#define WSTR 72

// one 64x128(A rows) x [128n x 64k](B) MMA pass per warp-tile layout:
// 8 warps as 2(M: mw) x 4(N: nw), each warp 32x32.
__device__ __forceinline__ void mma_tile(
    float acc[2][4][4],
    const char *AH, const char *AL, int kbase,
    const char *BH, const char *BL,
    int mw, int nw, int lane)
{
    const uint32_t aoff = (uint32_t)(((mw * 32 + (lane & 15)) * SSTR +
                                      kbase + (lane >> 4) * 8) * 2);
    const uint32_t boff = (uint32_t)(((nw * 32 + ((lane >> 4) & 1) * 8 + (lane & 7)) * WSTR +
                                      ((lane >> 3) & 1) * 8) * 2);
    const uint32_t aHb = (uint32_t)__cvta_generic_to_shared(AH) + aoff;
    const uint32_t aLb = (uint32_t)__cvta_generic_to_shared(AL) + aoff;
    const uint32_t bHb = (uint32_t)__cvta_generic_to_shared(BH) + boff;
    const uint32_t bLb = (uint32_t)__cvta_generic_to_shared(BL) + boff;

    #pragma unroll
    for (int kk = 0; kk < 4; kk++) {
        const uint32_t ka = kk * 32;   // 16 bf16 = 32 bytes
        uint32_t ah[2][4], al[2][4], bh[2][4], bl[2][4];
        ldsm4(ah[0], aHb + ka);
        ldsm4(ah[1], aHb + ka + 16 * SSTR * 2);
        ldsm4(al[0], aLb + ka);
        ldsm4(al[1], aLb + ka + 16 * SSTR * 2);
        ldsm4(bh[0], bHb + ka);
        ldsm4(bh[1], bHb + ka + 16 * WSTR * 2);
        ldsm4(bl[0], bLb + ka);
        ldsm4(bl[1], bLb + ka + 16 * WSTR * 2);
        #pragma unroll
        for (int j = 0; j < 4; j++) {
            const uint32_t *bp = &bh[j >> 1][2 * (j & 1)];
            mma_bf16(acc[0][j], ah[0], bp);
            mma_bf16(acc[1][j], ah[1], bp);
        }
        #pragma unroll
        for (int j = 0; j < 4; j++) {
            const uint32_t *bp = &bh[j >> 1][2 * (j & 1)];
            mma_bf16(acc[0][j], al[0], bp);
            mma_bf16(acc[1][j], al[1], bp);
        }
        #pragma unroll
        for (int j = 0; j < 4; j++) {
            const uint32_t *bp = &bl[j >> 1][2 * (j & 1)];
            mma_bf16(acc[0][j], ah[0], bp);
            mma_bf16(acc[1][j], ah[1], bp);
        }
    }
}

// cp.async load of a [128n x 64k] hi/lo W tile, 256 threads
__device__ __forceinline__ void loadW(
    char *smem_hi, char *smem_lo,
    const __nv_bfloat16 *WH, const __nv_bfloat16 *WL,
    int Kw, int nrow_base, int kofs, int tid)
{
    #pragma unroll
    for (int h = 0; h < 2; h++) {
        const int n = (tid >> 2) + h * 64;
        const int q = (tid & 3) * 16;
        const size_t g = (size_t)(nrow_base + n) * Kw + kofs + q;
        const uint32_t dh = (uint32_t)__cvta_generic_to_shared(smem_hi + (n * WSTR + q) * 2);
        const uint32_t dl = (uint32_t)__cvta_generic_to_shared(smem_lo + (n * WSTR + q) * 2);
        cp16(dh, WH + g);
        cp16(dh + 16, WH + g + 8);
        cp16(dl, WL + g);
        cp16(dl + 16, WL + g + 8);
    }
}

// A-phase helper: LN over 128 features in-register (4 threads/row)
__device__ __forceinline__ void ln_row(float4 v[8], const float *lnw,
                                       const float *lnb, int c0)
{
    float s = 0.f, q = 0.f;
    #pragma unroll
    for (int i = 0; i < 8; i++) {
        s += v[i].x + v[i].y + v[i].z + v[i].w;
        q += v[i].x * v[i].x + v[i].y * v[i].y + v[i].z * v[i].z + v[i].w * v[i].w;
    }
    s += __shfl_xor_sync(0xffffffffu, s, 1);
    s += __shfl_xor_sync(0xffffffffu, s, 2);
    q += __shfl_xor_sync(0xffffffffu, q, 1);
    q += __shfl_xor_sync(0xffffffffu, q, 2);
    const float m  = s * (1.f / 128.f);
    const float rs = rsqrtf(q * (1.f / 128.f) - m * m + 1e-5f);
    #pragma unroll
    for (int i = 0; i < 8; i++) {
        const int gc = c0 + 4 * i;
        v[i].x = (v[i].x - m) * rs * lnw[gc + 0] + lnb[gc + 0];
        v[i].y = (v[i].y - m) * rs * lnw[gc + 1] + lnb[gc + 1];
        v[i].z = (v[i].z - m) * rs * lnw[gc + 2] + lnb[gc + 2];
        v[i].w = (v[i].w - m) * rs * lnw[gc + 3] + lnb[gc + 3];
    }
}
__device__ __forceinline__ void store_split(uint32_t *AHu, uint32_t *ALu,
                                            const float4 v[8], int r, int c0)
{
    #pragma unroll
    for (int i = 0; i < 8; i++) {
        const int idx = (r * SSTR + c0 + 4 * i) >> 1;
        uint32_t h0, l0, h1, l1;
        split2(v[i].x, v[i].y, h0, l0);
        split2(v[i].z, v[i].w, h1, l1);
        AHu[idx] = h0; AHu[idx + 1] = h1;
        ALu[idx] = l0; ALu[idx + 1] = l1;
    }
}

// ======================= generic pipelined GEMM (64-row tiles) =============
#define G_AH 0
#define G_AL 17408
#define G_W  34816
#define G_SLOT 36864
#define G_TOT (G_W + 2 * G_SLOT)   // 108544

__global__ void __launch_bounds__(256, 2) tcgemm(
    const float *__restrict__ X, int ldx,
    const float *__restrict__ lnw, const float *__restrict__ lnb,
    const float *__restrict__ zdiv,
    const __nv_bfloat16 *__restrict__ WH, const __nv_bfloat16 *__restrict__ WL,
    int No, const float *__restrict__ bias, const float *__restrict__ resid,
    float *__restrict__ Y, int ldy, int R)
{
    extern __shared__ char smc[];
    char *AHc = smc + G_AH;
    char *ALc = smc + G_AL;
    uint32_t *AHu = reinterpret_cast<uint32_t *>(AHc);
    uint32_t *ALu = reinterpret_cast<uint32_t *>(ALc);

    const int tid  = threadIdx.x;
    const int wid  = tid >> 5;
    const int lane = tid & 31;
    const int mw   = wid & 1;
    const int nw   = wid >> 1;
    const int row0 = blockIdx.x * 64;
    const bool do_ln = (lnw != nullptr);
    const int T = (No >> 7) * 2;

    loadW(smc + G_W, smc + G_W + 18432, WH, WL, 128, 0, 0, tid); CP_COMMIT();
    loadW(smc + G_W + G_SLOT, smc + G_W + G_SLOT + 18432, WH, WL, 128, 0, 64, tid); CP_COMMIT();

    // ---- A: 64 rows, optional zdiv / LN, split ----------------------------
    {
        const int r  = tid >> 2;
        const int c0 = (tid & 3) * 32;
        const int grow = row0 + r;
        const bool valid = grow < R;
        float4 v[8];
        if (valid) {
            const float4 *xr = reinterpret_cast<const float4 *>(
                X + (size_t)grow * ldx + c0);
            #pragma unroll
            for (int i = 0; i < 8; i++) v[i] = xr[i];
        } else {
            #pragma unroll
            for (int i = 0; i < 8; i++) v[i] = make_float4(0.f, 0.f, 0.f, 0.f);
        }
        if (zdiv && valid) {
            const float rA = 1.f / (zdiv[(size_t)grow * 8 + (c0 >> 4)] + 1e-8f);
            const float rB = 1.f / (zdiv[(size_t)grow * 8 + (c0 >> 4) + 1] + 1e-8f);
            #pragma unroll
            for (int i = 0; i < 8; i++) {
                const float s = (i < 4) ? rA : rB;
                v[i].x *= s; v[i].y *= s; v[i].z *= s; v[i].w *= s;
            }
        }
        if (do_ln) ln_row(v, lnw, lnb, c0);
        store_split(AHu, ALu, v, r, c0);
    }

    float acc[2][4][4];
    for (int t = 0; t < T; t++) {
        const int nt = t >> 1;
        if (!(t & 1)) {
            #pragma unroll
            for (int mt = 0; mt < 2; mt++)
                #pragma unroll
                for (int j = 0; j < 4; j++)
                    #pragma unroll
                    for (int q = 0; q < 4; q++) acc[mt][j][q] = 0.f;
        }
        if (t < T - 1) { CP_WAIT(1); } else { CP_WAIT(0); }
        __syncthreads();
        char *sh = smc + G_W + (t & 1) * G_SLOT;
        mma_tile(acc, AHc, ALc, (t & 1) * 64, sh, sh + 18432, mw, nw, lane);
        __syncthreads();
        if (t + 2 < T) {
            loadW(sh, sh + 18432, WH, WL, 128, ((t + 2) >> 1) * 128,
                  ((t + 2) & 1) * 64, tid);
            CP_COMMIT();
        }
        if (t & 1) {
            #pragma unroll
            for (int mt = 0; mt < 2; mt++) {
                #pragma unroll
                for (int half = 0; half < 2; half++) {
                    const int r = row0 + mw * 32 + mt * 16 + (lane >> 2) + half * 8;
                    if (r < R) {
                        #pragma unroll
                        for (int j = 0; j < 4; j++) {
                            const int col = nt * 128 + nw * 32 + j * 8 + 2 * (lane & 3);
                            float2 o;
                            o.x = acc[mt][j][half * 2 + 0];
                            o.y = acc[mt][j][half * 2 + 1];
                            if (bias) { o.x += bias[col]; o.y += bias[col + 1]; }
                            const size_t yb = (size_t)r * ldy + col;
                            if (resid) { o.x += resid[yb]; o.y += resid[yb + 1]; }
                            *reinterpret_cast<float2 *>(Y + yb) = o;
                        }
                    }
                }
            }
        }
    }
}

// ======================= fused LN2 + MLP chain (64-row) ====================
#define C_AH 0
#define C_AL 17408
#define C_HH 34816
#define C_HL 52224
#define C_W  69632
#define C_TOT 106496

__global__ void __launch_bounds__(256, 2) mlp_chain(
    float *__restrict__ Y,
    const float *__restrict__ lnw, const float *__restrict__ lnb,
    const __nv_bfloat16 *__restrict__ W1H, const __nv_bfloat16 *__restrict__ W1L,
    const __nv_bfloat16 *__restrict__ W2H, const __nv_bfloat16 *__restrict__ W2L,
    int R)
{
    extern __shared__ char smc[];
    char *AHc = smc + C_AH;  char *ALc = smc + C_AL;
    char *HHc = smc + C_HH;  char *HLc = smc + C_HL;
    uint32_t *AHu = reinterpret_cast<uint32_t *>(AHc);
    uint32_t *ALu = reinterpret_cast<uint32_t *>(ALc);
    uint32_t *HHu = reinterpret_cast<uint32_t *>(HHc);
    uint32_t *HLu = reinterpret_cast<uint32_t *>(HLc);
    char *wh = smc + C_W;  char *wl = smc + C_W + 18432;

    const int tid  = threadIdx.x;
    const int wid  = tid >> 5;
    const int lane = tid & 31;
    const int mw   = wid & 1;
    const int nw   = wid >> 1;
    const int row0 = blockIdx.x * 64;

    // first W tile prefetch overlaps A-phase
    loadW(wh, wl, W1H, W1L, 128, 0, 0, tid); CP_COMMIT();

    // ---- A: 64 rows + LN2, split -----------------------------------------
    {
        const int r  = tid >> 2;
        const int c0 = (tid & 3) * 32;
        const int grow = row0 + r;
        const bool valid = grow < R;
        float4 v[8];
        if (valid) {
            const float4 *xr = reinterpret_cast<const float4 *>(
                Y + (size_t)grow * 128 + c0);
            #pragma unroll
            for (int i = 0; i < 8; i++) v[i] = xr[i];
        } else {
            #pragma unroll
            for (int i = 0; i < 8; i++) v[i] = make_float4(0.f, 0.f, 0.f, 0.f);
        }
        ln_row(v, lnw, lnb, c0);
        store_split(AHu, ALu, v, r, c0);
    }

    float acc1[2][4][4], acc2[2][4][4];
    #pragma unroll
    for (int mt = 0; mt < 2; mt++)
        #pragma unroll
        for (int j = 0; j < 4; j++)
            #pragma unroll
            for (int q = 0; q < 4; q++) acc2[mt][j][q] = 0.f;

    #pragma unroll
    for (int h = 0; h < 2; h++) {
        #pragma unroll
        for (int mt = 0; mt < 2; mt++)
            #pragma unroll
            for (int j = 0; j < 4; j++)
                #pragma unroll
                for (int q = 0; q < 4; q++) acc1[mt][j][q] = 0.f;

        // W1 half h (tile k0 prefetched for h=0 before A phase)
        if (h == 1) { loadW(wh, wl, W1H, W1L, 128, 128, 0, tid); CP_COMMIT(); }
        CP_WAIT(0); __syncthreads();
        mma_tile(acc1, AHc, ALc, 0, wh, wl, mw, nw, lane);
        __syncthreads();
        loadW(wh, wl, W1H, W1L, 128, h * 128, 64, tid); CP_COMMIT();
        CP_WAIT(0); __syncthreads();
        mma_tile(acc1, AHc, ALc, 64, wh, wl, mw, nw, lane);

        // silu -> H (64 x 128 for this half)
        #pragma unroll
        for (int mt = 0; mt < 2; mt++)
            #pragma unroll
            for (int qh = 0; qh < 2; qh++)
                #pragma unroll
                for (int j = 0; j < 4; j++) {
                    const int rl = mw * 32 + mt * 16 + (lane >> 2) + qh * 8;
                    const int cl = nw * 32 + j * 8 + 2 * (lane & 3);
                    float x = acc1[mt][j][qh * 2 + 0];
                    float y = acc1[mt][j][qh * 2 + 1];
                    x = x / (1.f + __expf(-x));
                    y = y / (1.f + __expf(-y));
                    uint32_t hh, ll;
                    split2(x, y, hh, ll);
                    const int idx = (rl * SSTR + cl) >> 1;
                    HHu[idx] = hh; HLu[idx] = ll;
                }
        __syncthreads();

        // acc2 += H @ W2[:, h*128 : h*128+128]
        loadW(wh, wl, W2H, W2L, 256, 0, h * 128, tid); CP_COMMIT();
        CP_WAIT(0); __syncthreads();
        mma_tile(acc2, HHc, HLc, 0, wh, wl, mw, nw, lane);
        __syncthreads();
        loadW(wh, wl, W2H, W2L, 256, 0, h * 128 + 64, tid); CP_COMMIT();
        CP_WAIT(0); __syncthreads();
        mma_tile(acc2, HHc, HLc, 64, wh, wl, mw, nw, lane);
        __syncthreads();
    }

    #pragma unroll
    for (int mt = 0; mt < 2; mt++) {
        #pragma unroll
        for (int half = 0; half < 2; half++) {
            const int r = row0 + mw * 32 + mt * 16 + (lane >> 2) + half * 8;
            if (r < R) {
                #pragma unroll
                for (int j = 0; j < 4; j++) {
                    const int col = nw * 32 + j * 8 + 2 * (lane & 3);
                    const size_t yb = (size_t)r * 128 + col;
                    float2 o;
                    o.x = acc2[mt][j][half * 2 + 0] + Y[yb];
                    o.y = acc2[mt][j][half * 2 + 1] + Y[yb + 1];
                    *reinterpret_cast<float2 *>(Y + yb) = o;
                }
            }
        }
    }
}

// ======================= fused edge attention + Wo_e (64-row) ==============
#define T_AH 0
#define T_AL 17408
#define T_W  34816
#define T_SLOT 36864
#define T_TOT (T_W + 2 * T_SLOT)   // 108544

__global__ void __launch_bounds__(256, 2) attn_gemm(
    const float *__restrict__ P, const float *__restrict__ QKV,
    const int *__restrict__ src, const int *__restrict__ dst,
    const __nv_bfloat16 *__restrict__ WH, const __nv_bfloat16 *__restrict__ WL,
    const float *__restrict__ bias, const float *__restrict__ resid,
    float *__restrict__ wV, float *__restrict__ z,
    float *__restrict__ Y)
{
    extern __shared__ char smc[];
    char *AHc = smc + T_AH;  char *ALc = smc + T_AL;
    uint32_t *AHu = reinterpret_cast<uint32_t *>(AHc);
    uint32_t *ALu = reinterpret_cast<uint32_t *>(ALc);
    char *w0h = smc + T_W;            char *w0l = smc + T_W + 18432;
    char *w1h = smc + T_W + T_SLOT;   char *w1l = smc + T_W + T_SLOT + 18432;

    const int tid  = threadIdx.x;
    const int wid  = tid >> 5;
    const int lane = tid & 31;
    const int mw   = wid & 1;
    const int nw   = wid >> 1;
    const int row0 = blockIdx.x * 64;

    loadW(w0h, w0l, WH, WL, 128, 0, 0, tid);  CP_COMMIT();
    loadW(w1h, w1l, WH, WL, 128, 0, 64, tid); CP_COMMIT();

    // ---- A phase: per-edge attention, e_out straight into smem -----------
    {
        const int r  = tid >> 2;
        const int c0 = (tid & 3) * 32;
        const int e  = row0 + r;
        float4 eo[8];
        if (e < EE) {
            const int s = src[e];
            const int d = dst[e];
            const float4 *pr = reinterpret_cast<const float4 *>(P + (size_t)e * 128 + c0);
            const float4 *kr = reinterpret_cast<const float4 *>(QKV + (size_t)s * 384 + 128 + c0);
            const float4 *qr = reinterpret_cast<const float4 *>(QKV + (size_t)d * 384 + c0);
            float sA = 0.f, sB = 0.f;
            #pragma unroll
            for (int i = 0; i < 8; i++) {
                const float4 kv = kr[i];
                const float4 qv = qr[i];
                const float4 pv = pr[i];
                float4 t;
                t.x = CLIP5(kv.x * qv.x * 0.25f) * pv.x;
                t.y = CLIP5(kv.y * qv.y * 0.25f) * pv.y;
                t.z = CLIP5(kv.z * qv.z * 0.25f) * pv.z;
                t.w = CLIP5(kv.w * qv.w * 0.25f) * pv.w;
                eo[i] = t;
                const float ts = t.x + t.y + t.z + t.w;
                if (i < 4) sA += ts; else sB += ts;
            }
            const float wA = __expf(CLIP5(sA));
            const float wB = __expf(CLIP5(sB));
            const float4 *vr = reinterpret_cast<const float4 *>(QKV + (size_t)s * 384 + 256 + c0);
            float *wvp = wV + (size_t)d * 128 + c0;
            #pragma unroll
            for (int i = 0; i < 8; i++) {
                const float w = (i < 4) ? wA : wB;
                const float4 vv = vr[i];
                atomicAdd(wvp + 4 * i + 0, vv.x * w);
                atomicAdd(wvp + 4 * i + 1, vv.y * w);
                atomicAdd(wvp + 4 * i + 2, vv.z * w);
                atomicAdd(wvp + 4 * i + 3, vv.w * w);
            }
            atomicAdd(z + (size_t)d * 8 + (c0 >> 4), wA);
            atomicAdd(z + (size_t)d * 8 + (c0 >> 4) + 1, wB);
        } else {
            #pragma unroll
            for (int i = 0; i < 8; i++) eo[i] = make_float4(0.f, 0.f, 0.f, 0.f);
        }
        store_split(AHu, ALu, eo, tid >> 2, c0);
    }

    float acc[2][4][4];
    #pragma unroll
    for (int mt = 0; mt < 2; mt++)
        #pragma unroll
        for (int j = 0; j < 4; j++)
            #pragma unroll
            for (int q = 0; q < 4; q++) acc[mt][j][q] = 0.f;

    CP_WAIT(1); __syncthreads();
    mma_tile(acc, AHc, ALc, 0, w0h, w0l, mw, nw, lane);
    CP_WAIT(0); __syncthreads();
    mma_tile(acc, AHc, ALc, 64, w1h, w1l, mw, nw, lane);

    #pragma unroll
    for (int mt = 0; mt < 2; mt++) {
        #pragma unroll
        for (int half = 0; half < 2; half++) {
            const int r = row0 + mw * 32 + mt * 16 + (lane >> 2) + half * 8;
            if (r < EE) {
                #pragma unroll
                for (int j = 0; j < 4; j++) {
                    const int col = nw * 32 + j * 8 + 2 * (lane & 3);
                    const size_t yb = (size_t)r * 128 + col;
                    float2 o;
                    o.x = acc[mt][j][half * 2 + 0] + bias[col] + resid[yb];
                    o.y = acc[mt][j][half * 2 + 1] + bias[col + 1] + resid[yb + 1];
                    *reinterpret_cast<float2 *>(Y + yb) = o;
                }
            }
        }
    }
}

// ---------------------------------------------------------------------------
__global__ void split_w(const float *__restrict__ W,
                        __nv_bfloat16 *__restrict__ H,
                        __nv_bfloat16 *__restrict__ L, int K, int No)
{
    const int i = blockIdx.x * 256 + threadIdx.x;
    if (i < K * No) {
        const int k = i / No;
        const int n = i - k * No;
        const float v = W[i];
        const __nv_bfloat16 h = __float2bfloat16(v);
        H[(size_t)n * K + k] = h;
        L[(size_t)n * K + k] = __float2bfloat16(v - __bfloat162float(h));
    }
}

__global__ void pack_bias(const float *__restrict__ a, const float *__restrict__ b,
                          const float *__restrict__ c, float *__restrict__ o)
{
    const int i = threadIdx.x;
    if (i < 128) { o[i] = a[i]; o[128 + i] = b[i]; o[256 + i] = c[i]; }
}

// ---------------------------------------------------------------------------
extern "C" void kernel_launch(void *const *d_in, const int *in_sizes, int n_in,
                              void *d_out, int out_size)
{
    const float *node   = (const float *)d_in[0];
    const float *edge   = (const float *)d_in[1];
    const int   *src    = (const int *)d_in[2];
    const int   *dst    = (const int *)d_in[3];
    const float *ln1n_w = (const float *)d_in[4];
    const float *ln1n_b = (const float *)d_in[5];
    const float *ln1e_w = (const float *)d_in[6];
    const float *ln1e_b = (const float *)d_in[7];
    const float *ln2n_w = (const float *)d_in[8];
    const float *ln2n_b = (const float *)d_in[9];
    const float *ln2e_w = (const float *)d_in[10];
    const float *ln2e_b = (const float *)d_in[11];
    const float *Wq = (const float *)d_in[12];  const float *bq = (const float *)d_in[13];
    const float *Wk = (const float *)d_in[14];  const float *bk = (const float *)d_in[15];
    const float *Wv = (const float *)d_in[16];  const float *bv = (const float *)d_in[17];
    const float *We = (const float *)d_in[18];  const float *be = (const float *)d_in[19];
    const float *Wo_n = (const float *)d_in[20]; const float *bo_n = (const float *)d_in[21];
    const float *Wo_e = (const float *)d_in[22]; const float *bo_e = (const float *)d_in[23];
    const float *w1n = (const float *)d_in[24];
    const float *w2n = (const float *)d_in[25];
    const float *w1e = (const float *)d_in[26];
    const float *w2e = (const float *)d_in[27];

    float *outh = (float *)d_out;
    float *oute = outh + (size_t)NN * DD;

    float *QKVp, *Pp, *wVp, *zp, *bqkv;
    __nv_bfloat16 *WHp, *WLp;
    cudaGetSymbolAddress((void **)&QKVp, g_QKV);
    cudaGetSymbolAddress((void **)&Pp,  g_P);
    cudaGetSymbolAddress((void **)&wVp, g_wV);
    cudaGetSymbolAddress((void **)&zp,  g_z);
    cudaGetSymbolAddress((void **)&bqkv, g_bqkv);
    cudaGetSymbolAddress((void **)&WHp, g_WH);
    cudaGetSymbolAddress((void **)&WLp, g_WL);

    cudaFuncSetAttribute(tcgemm,    cudaFuncAttributeMaxDynamicSharedMemorySize, G_TOT);
    cudaFuncSetAttribute(mlp_chain, cudaFuncAttributeMaxDynamicSharedMemorySize, C_TOT);
    cudaFuncSetAttribute(attn_gemm, cudaFuncAttributeMaxDynamicSharedMemorySize, T_TOT);

    auto SW = [&](const float *W, int ofs, int K, int No) {
        split_w<<<(K * No + 255) / 256, 256>>>(W, WHp + ofs, WLp + ofs, K, No);
    };
    SW(Wq, OF_QKV, 128, 128);
    SW(Wk, OF_QKV + 128 * 128, 128, 128);
    SW(Wv, OF_QKV + 256 * 128, 128, 128);
    SW(We, OF_WE, 128, 128);
    SW(Wo_n, OF_WON, 128, 128);
    SW(Wo_e, OF_WOE, 128, 128);
    SW(w1n, OF_W1N, 128, 256);
    SW(w2n, OF_W2N, 256, 128);
    SW(w1e, OF_W1E, 128, 256);
    SW(w2e, OF_W2E, 256, 128);
    pack_bias<<<1, 128>>>(bq, bk, bv, bqkv);

    cudaMemsetAsync(wVp, 0, (size_t)NN * DD * sizeof(float), 0);
    cudaMemsetAsync(zp,  0, (size_t)NN * HH * sizeof(float), 0);

    const int GN = (NN + 63) / 64;
    const int GE = (EE + 63) / 64;

    // LN1 + fused QKV projection (No=384); LN1 + edge projection -> P
    tcgemm<<<GN, 256, G_TOT>>>(node, 128, ln1n_w, ln1n_b, nullptr,
                               WHp + OF_QKV, WLp + OF_QKV, 384, bqkv, nullptr,
                               QKVp, 384, NN);
    tcgemm<<<GE, 256, G_TOT>>>(edge, 128, ln1e_w, ln1e_b, nullptr,
                               WHp + OF_WE, WLp + OF_WE, 128, be, nullptr,
                               Pp, 128, EE);

    // fused edge attention + Wo_e + resid -> oute (also scatters wV, z)
    attn_gemm<<<GE, 256, T_TOT>>>(Pp, QKVp, src, dst,
                                  WHp + OF_WOE, WLp + OF_WOE, bo_e, edge,
                                  wVp, zp, oute);

    // node output projection: A = wV / z, + resid -> outh
    tcgemm<<<GN, 256, G_TOT>>>(wVp, 128, nullptr, nullptr, zp,
                               WHp + OF_WON, WLp + OF_WON, 128, bo_n, node,
                               outh, 128, NN);

    // fused LN2 + MLP + resid, in place
    mlp_chain<<<GN, 256, C_TOT>>>(outh, ln2n_w, ln2n_b,
                                  WHp + OF_W1N, WLp + OF_W1N,
                                  WHp + OF_W2N, WLp + OF_W2N, NN);
    mlp_chain<<<GE, 256, C_TOT>>>(oute, ln2e_w, ln2e_b,
                                  WHp + OF_W1E, WLp + OF_W1E,
                                  WHp + OF_W2E, WLp + OF_W2E, EE);
}

// round 9
// speedup vs baseline: 1.5203x; 1.5203x over previous
#include <cuda_runtime.h>
#include <cuda_fp16.h>
#include <cstdint>

#define NN 50000
#define EE 800000
#define DD 128
#define HH 8

// ---------------- scratch (static device arrays; no allocation) ------------
__device__ float g_QKV[(size_t)NN * 384];
__device__ float g_P [(size_t)EE * DD];      // proj_e
__device__ float g_wV[(size_t)NN * DD];
__device__ float g_z [(size_t)NN * HH];
__device__ float g_bqkv[384];

// fp16 weights, [n][k] layout, packed
#define OF_QKV  0                      // 384 x 128
#define OF_WE   49152                  // 128 x 128
#define OF_WON  65536
#define OF_WOE  81920
#define OF_W1N  98304                  // 256 x 128
#define OF_W2N  131072                 // 128 x 256
#define OF_W1E  163840
#define OF_W2E  196608
#define W_TOT   229376
__device__ __half g_WF[W_TOT];

// =================== helpers ===============================================
__device__ __forceinline__ void mma_f16(float *c, const uint32_t *a,
                                        const uint32_t *b) {
    asm volatile(
        "mma.sync.aligned.m16n8k16.row.col.f32.f16.f16.f32 "
        "{%0,%1,%2,%3}, {%4,%5,%6,%7}, {%8,%9}, {%0,%1,%2,%3};"
        : "+f"(c[0]), "+f"(c[1]), "+f"(c[2]), "+f"(c[3])
        : "r"(a[0]), "r"(a[1]), "r"(a[2]), "r"(a[3]), "r"(b[0]), "r"(b[1]));
}
__device__ __forceinline__ void ldsm4(uint32_t *r, uint32_t addr) {
    asm volatile("ldmatrix.sync.aligned.m8n8.x4.shared.b16 {%0,%1,%2,%3}, [%4];"
                 : "=r"(r[0]), "=r"(r[1]), "=r"(r[2]), "=r"(r[3]) : "r"(addr));
}
__device__ __forceinline__ uint32_t pack_h2(float x, float y) {
    __half2 t = __floats2half2_rn(x, y);
    return *reinterpret_cast<uint32_t *>(&t);
}
__device__ __forceinline__ void cp16(uint32_t saddr, const void *g) {
    asm volatile("cp.async.cg.shared.global [%0], [%1], 16;"
                 :: "r"(saddr), "l"(g));
}
#define CP_COMMIT() asm volatile("cp.async.commit_group;" ::: "memory")
#define CP_WAIT(n)  asm volatile("cp.async.wait_group %0;" :: "n"(n) : "memory")
#define CLIP5(x) fminf(fmaxf((x), -5.f), 5.f)

// A-style smem stride (fp16), W-buffer stride (fp16, 64-k tiles)
#define SSTR 136
#define WSTR 72

// one 64x128(A rows) x [128n x 64k](B) fp16 MMA pass:
// 8 warps as 2(M: mw) x 4(N: nw), each warp 32x32.
__device__ __forceinline__ void mma_tile(
    float acc[2][4][4],
    const char *A, int kbase, const char *B,
    int mw, int nw, int lane)
{
    const uint32_t aoff = (uint32_t)(((mw * 32 + (lane & 15)) * SSTR +
                                      kbase + (lane >> 4) * 8) * 2);
    const uint32_t boff = (uint32_t)(((nw * 32 + ((lane >> 4) & 1) * 8 + (lane & 7)) * WSTR +
                                      ((lane >> 3) & 1) * 8) * 2);
    const uint32_t aB = (uint32_t)__cvta_generic_to_shared(A) + aoff;
    const uint32_t bB = (uint32_t)__cvta_generic_to_shared(B) + boff;

    #pragma unroll
    for (int kk = 0; kk < 4; kk++) {
        const uint32_t ka = kk * 32;   // 16 fp16 = 32 bytes
        uint32_t a[2][4], b[2][4];
        ldsm4(a[0], aB + ka);
        ldsm4(a[1], aB + ka + 16 * SSTR * 2);
        ldsm4(b[0], bB + ka);
        ldsm4(b[1], bB + ka + 16 * WSTR * 2);
        #pragma unroll
        for (int j = 0; j < 4; j++) {
            const uint32_t *bp = &b[j >> 1][2 * (j & 1)];
            mma_f16(acc[0][j], a[0], bp);
            mma_f16(acc[1][j], a[1], bp);
        }
    }
}

// cp.async load of a [128n x 64k] fp16 W tile, 256 threads
__device__ __forceinline__ void loadW(
    char *smem_w, const __half *W,
    int Kw, int nrow_base, int kofs, int tid)
{
    #pragma unroll
    for (int h = 0; h < 2; h++) {
        const int n = (tid >> 2) + h * 64;
        const int q = (tid & 3) * 16;
        const size_t g = (size_t)(nrow_base + n) * Kw + kofs + q;
        const uint32_t d = (uint32_t)__cvta_generic_to_shared(smem_w + (n * WSTR + q) * 2);
        cp16(d, W + g);
        cp16(d + 16, W + g + 8);
    }
}

// LN over 128 features in-register (4 threads/row)
__device__ __forceinline__ void ln_row(float4 v[8], const float *lnw,
                                       const float *lnb, int c0)
{
    float s = 0.f, q = 0.f;
    #pragma unroll
    for (int i = 0; i < 8; i++) {
        s += v[i].x + v[i].y + v[i].z + v[i].w;
        q += v[i].x * v[i].x + v[i].y * v[i].y + v[i].z * v[i].z + v[i].w * v[i].w;
    }
    s += __shfl_xor_sync(0xffffffffu, s, 1);
    s += __shfl_xor_sync(0xffffffffu, s, 2);
    q += __shfl_xor_sync(0xffffffffu, q, 1);
    q += __shfl_xor_sync(0xffffffffu, q, 2);
    const float m  = s * (1.f / 128.f);
    const float rs = rsqrtf(q * (1.f / 128.f) - m * m + 1e-5f);
    #pragma unroll
    for (int i = 0; i < 8; i++) {
        const int gc = c0 + 4 * i;
        v[i].x = (v[i].x - m) * rs * lnw[gc + 0] + lnb[gc + 0];
        v[i].y = (v[i].y - m) * rs * lnw[gc + 1] + lnb[gc + 1];
        v[i].z = (v[i].z - m) * rs * lnw[gc + 2] + lnb[gc + 2];
        v[i].w = (v[i].w - m) * rs * lnw[gc + 3] + lnb[gc + 3];
    }
}
__device__ __forceinline__ void store_cvt(uint32_t *Au, const float4 v[8],
                                          int r, int c0)
{
    #pragma unroll
    for (int i = 0; i < 8; i++) {
        const int idx = (r * SSTR + c0 + 4 * i) >> 1;
        Au[idx]     = pack_h2(v[i].x, v[i].y);
        Au[idx + 1] = pack_h2(v[i].z, v[i].w);
    }
}

// ======================= generic pipelined GEMM (64-row tiles) =============
#define G_A  0
#define G_W  17408
#define G_SLOT 18432
#define G_TOT (G_W + 2 * G_SLOT)   // 54272

__global__ void __launch_bounds__(256, 3) tcgemm(
    const float *__restrict__ X, int ldx,
    const float *__restrict__ lnw, const float *__restrict__ lnb,
    const float *__restrict__ zdiv,
    const __half *__restrict__ W,
    int No, const float *__restrict__ bias, const float *__restrict__ resid,
    float *__restrict__ Y, int ldy, int R)
{
    extern __shared__ char smc[];
    char *Ac = smc + G_A;
    uint32_t *Au = reinterpret_cast<uint32_t *>(Ac);

    const int tid  = threadIdx.x;
    const int wid  = tid >> 5;
    const int lane = tid & 31;
    const int mw   = wid & 1;
    const int nw   = wid >> 1;
    const int row0 = blockIdx.x * 64;
    const bool do_ln = (lnw != nullptr);
    const int T = (No >> 7) * 2;

    loadW(smc + G_W,          W, 128, 0, 0, tid);  CP_COMMIT();
    loadW(smc + G_W + G_SLOT, W, 128, 0, 64, tid); CP_COMMIT();

    // ---- A: 64 rows, optional zdiv / LN, cvt to fp16 ----------------------
    {
        const int r  = tid >> 2;
        const int c0 = (tid & 3) * 32;
        const int grow = row0 + r;
        const bool valid = grow < R;
        float4 v[8];
        if (valid) {
            const float4 *xr = reinterpret_cast<const float4 *>(
                X + (size_t)grow * ldx + c0);
            #pragma unroll
            for (int i = 0; i < 8; i++) v[i] = xr[i];
        } else {
            #pragma unroll
            for (int i = 0; i < 8; i++) v[i] = make_float4(0.f, 0.f, 0.f, 0.f);
        }
        if (zdiv && valid) {
            const float rA = 1.f / (zdiv[(size_t)grow * 8 + (c0 >> 4)] + 1e-8f);
            const float rB = 1.f / (zdiv[(size_t)grow * 8 + (c0 >> 4) + 1] + 1e-8f);
            #pragma unroll
            for (int i = 0; i < 8; i++) {
                const float s = (i < 4) ? rA : rB;
                v[i].x *= s; v[i].y *= s; v[i].z *= s; v[i].w *= s;
            }
        }
        if (do_ln) ln_row(v, lnw, lnb, c0);
        store_cvt(Au, v, r, c0);
    }

    float acc[2][4][4];
    for (int t = 0; t < T; t++) {
        const int nt = t >> 1;
        if (!(t & 1)) {
            #pragma unroll
            for (int mt = 0; mt < 2; mt++)
                #pragma unroll
                for (int j = 0; j < 4; j++)
                    #pragma unroll
                    for (int q = 0; q < 4; q++) acc[mt][j][q] = 0.f;
        }
        if (t < T - 1) { CP_WAIT(1); } else { CP_WAIT(0); }
        __syncthreads();
        char *sh = smc + G_W + (t & 1) * G_SLOT;
        mma_tile(acc, Ac, (t & 1) * 64, sh, mw, nw, lane);
        __syncthreads();
        if (t + 2 < T) {
            loadW(sh, W, 128, ((t + 2) >> 1) * 128, ((t + 2) & 1) * 64, tid);
            CP_COMMIT();
        }
        if (t & 1) {
            #pragma unroll
            for (int mt = 0; mt < 2; mt++) {
                #pragma unroll
                for (int half = 0; half < 2; half++) {
                    const int r = row0 + mw * 32 + mt * 16 + (lane >> 2) + half * 8;
                    if (r < R) {
                        #pragma unroll
                        for (int j = 0; j < 4; j++) {
                            const int col = nt * 128 + nw * 32 + j * 8 + 2 * (lane & 3);
                            float2 o;
                            o.x = acc[mt][j][half * 2 + 0];
                            o.y = acc[mt][j][half * 2 + 1];
                            if (bias) { o.x += bias[col]; o.y += bias[col + 1]; }
                            const size_t yb = (size_t)r * ldy + col;
                            if (resid) { o.x += resid[yb]; o.y += resid[yb + 1]; }
                            *reinterpret_cast<float2 *>(Y + yb) = o;
                        }
                    }
                }
            }
        }
    }
}

// ======================= fused LN2 + MLP chain (64-row) ====================
#define C_A  0
#define C_H  17408
#define C_W  34816
#define C_TOT 53248

__global__ void __launch_bounds__(256, 3) mlp_chain(
    float *__restrict__ Y,
    const float *__restrict__ lnw, const float *__restrict__ lnb,
    const __half *__restrict__ W1, const __half *__restrict__ W2,
    int R)
{
    extern __shared__ char smc[];
    char *Ac = smc + C_A;  char *Hc = smc + C_H;
    uint32_t *Au = reinterpret_cast<uint32_t *>(Ac);
    uint32_t *Hu = reinterpret_cast<uint32_t *>(Hc);
    char *wc = smc + C_W;

    const int tid  = threadIdx.x;
    const int wid  = tid >> 5;
    const int lane = tid & 31;
    const int mw   = wid & 1;
    const int nw   = wid >> 1;
    const int row0 = blockIdx.x * 64;

    loadW(wc, W1, 128, 0, 0, tid); CP_COMMIT();

    // ---- A: 64 rows + LN2, cvt -------------------------------------------
    {
        const int r  = tid >> 2;
        const int c0 = (tid & 3) * 32;
        const int grow = row0 + r;
        const bool valid = grow < R;
        float4 v[8];
        if (valid) {
            const float4 *xr = reinterpret_cast<const float4 *>(
                Y + (size_t)grow * 128 + c0);
            #pragma unroll
            for (int i = 0; i < 8; i++) v[i] = xr[i];
        } else {
            #pragma unroll
            for (int i = 0; i < 8; i++) v[i] = make_float4(0.f, 0.f, 0.f, 0.f);
        }
        ln_row(v, lnw, lnb, c0);
        store_cvt(Au, v, r, c0);
    }

    float acc1[2][4][4], acc2[2][4][4];
    #pragma unroll
    for (int mt = 0; mt < 2; mt++)
        #pragma unroll
        for (int j = 0; j < 4; j++)
            #pragma unroll
            for (int q = 0; q < 4; q++) acc2[mt][j][q] = 0.f;

    #pragma unroll
    for (int h = 0; h < 2; h++) {
        #pragma unroll
        for (int mt = 0; mt < 2; mt++)
            #pragma unroll
            for (int j = 0; j < 4; j++)
                #pragma unroll
                for (int q = 0; q < 4; q++) acc1[mt][j][q] = 0.f;

        if (h == 1) { loadW(wc, W1, 128, 128, 0, tid); CP_COMMIT(); }
        CP_WAIT(0); __syncthreads();
        mma_tile(acc1, Ac, 0, wc, mw, nw, lane);
        __syncthreads();
        loadW(wc, W1, 128, h * 128, 64, tid); CP_COMMIT();
        CP_WAIT(0); __syncthreads();
        mma_tile(acc1, Ac, 64, wc, mw, nw, lane);

        // silu -> H (64 x 128 for this half)
        #pragma unroll
        for (int mt = 0; mt < 2; mt++)
            #pragma unroll
            for (int qh = 0; qh < 2; qh++)
                #pragma unroll
                for (int j = 0; j < 4; j++) {
                    const int rl = mw * 32 + mt * 16 + (lane >> 2) + qh * 8;
                    const int cl = nw * 32 + j * 8 + 2 * (lane & 3);
                    float x = acc1[mt][j][qh * 2 + 0];
                    float y = acc1[mt][j][qh * 2 + 1];
                    x = x / (1.f + __expf(-x));
                    y = y / (1.f + __expf(-y));
                    Hu[(rl * SSTR + cl) >> 1] = pack_h2(x, y);
                }
        __syncthreads();

        // acc2 += H @ W2[:, h*128 : h*128+128]
        loadW(wc, W2, 256, 0, h * 128, tid); CP_COMMIT();
        CP_WAIT(0); __syncthreads();
        mma_tile(acc2, Hc, 0, wc, mw, nw, lane);
        __syncthreads();
        loadW(wc, W2, 256, 0, h * 128 + 64, tid); CP_COMMIT();
        CP_WAIT(0); __syncthreads();
        mma_tile(acc2, Hc, 64, wc, mw, nw, lane);
        __syncthreads();
    }

    #pragma unroll
    for (int mt = 0; mt < 2; mt++) {
        #pragma unroll
        for (int half = 0; half < 2; half++) {
            const int r = row0 + mw * 32 + mt * 16 + (lane >> 2) + half * 8;
            if (r < R) {
                #pragma unroll
                for (int j = 0; j < 4; j++) {
                    const int col = nw * 32 + j * 8 + 2 * (lane & 3);
                    const size_t yb = (size_t)r * 128 + col;
                    float2 o;
                    o.x = acc2[mt][j][half * 2 + 0] + Y[yb];
                    o.y = acc2[mt][j][half * 2 + 1] + Y[yb + 1];
                    *reinterpret_cast<float2 *>(Y + yb) = o;
                }
            }
        }
    }
}

// ======================= fused edge attention + Wo_e (64-row) ==============
#define T_A  0
#define T_W  17408
#define T_SLOT 18432
#define T_TOT (T_W + 2 * T_SLOT)   // 54272

__global__ void __launch_bounds__(256, 3) attn_gemm(
    const float *__restrict__ P, const float *__restrict__ QKV,
    const int *__restrict__ src, const int *__restrict__ dst,
    const __half *__restrict__ W,
    const float *__restrict__ bias, const float *__restrict__ resid,
    float *__restrict__ wV, float *__restrict__ z,
    float *__restrict__ Y)
{
    extern __shared__ char smc[];
    char *Ac = smc + T_A;
    uint32_t *Au = reinterpret_cast<uint32_t *>(Ac);
    char *w0 = smc + T_W;
    char *w1 = smc + T_W + T_SLOT;

    const int tid  = threadIdx.x;
    const int wid  = tid >> 5;
    const int lane = tid & 31;
    const int mw   = wid & 1;
    const int nw   = wid >> 1;
    const int row0 = blockIdx.x * 64;

    loadW(w0, W, 128, 0, 0, tid);  CP_COMMIT();
    loadW(w1, W, 128, 0, 64, tid); CP_COMMIT();

    // ---- A phase: per-edge attention, e_out straight into smem -----------
    {
        const int r  = tid >> 2;
        const int c0 = (tid & 3) * 32;
        const int e  = row0 + r;
        float4 eo[8];
        if (e < EE) {
            const int s = src[e];
            const int d = dst[e];
            const float4 *pr = reinterpret_cast<const float4 *>(P + (size_t)e * 128 + c0);
            const float4 *kr = reinterpret_cast<const float4 *>(QKV + (size_t)s * 384 + 128 + c0);
            const float4 *qr = reinterpret_cast<const float4 *>(QKV + (size_t)d * 384 + c0);
            float sA = 0.f, sB = 0.f;
            #pragma unroll
            for (int i = 0; i < 8; i++) {
                const float4 kv = kr[i];
                const float4 qv = qr[i];
                const float4 pv = pr[i];
                float4 t;
                t.x = CLIP5(kv.x * qv.x * 0.25f) * pv.x;
                t.y = CLIP5(kv.y * qv.y * 0.25f) * pv.y;
                t.z = CLIP5(kv.z * qv.z * 0.25f) * pv.z;
                t.w = CLIP5(kv.w * qv.w * 0.25f) * pv.w;
                eo[i] = t;
                const float ts = t.x + t.y + t.z + t.w;
                if (i < 4) sA += ts; else sB += ts;
            }
            const float wA = __expf(CLIP5(sA));
            const float wB = __expf(CLIP5(sB));
            const float4 *vr = reinterpret_cast<const float4 *>(QKV + (size_t)s * 384 + 256 + c0);
            float *wvp = wV + (size_t)d * 128 + c0;
            #pragma unroll
            for (int i = 0; i < 8; i++) {
                const float w = (i < 4) ? wA : wB;
                const float4 vv = vr[i];
                atomicAdd(wvp + 4 * i + 0, vv.x * w);
                atomicAdd(wvp + 4 * i + 1, vv.y * w);
                atomicAdd(wvp + 4 * i + 2, vv.z * w);
                atomicAdd(wvp + 4 * i + 3, vv.w * w);
            }
            atomicAdd(z + (size_t)d * 8 + (c0 >> 4), wA);
            atomicAdd(z + (size_t)d * 8 + (c0 >> 4) + 1, wB);
        } else {
            #pragma unroll
            for (int i = 0; i < 8; i++) eo[i] = make_float4(0.f, 0.f, 0.f, 0.f);
        }
        store_cvt(Au, eo, tid >> 2, c0);
    }

    float acc[2][4][4];
    #pragma unroll
    for (int mt = 0; mt < 2; mt++)
        #pragma unroll
        for (int j = 0; j < 4; j++)
            #pragma unroll
            for (int q = 0; q < 4; q++) acc[mt][j][q] = 0.f;

    CP_WAIT(1); __syncthreads();
    mma_tile(acc, Ac, 0, w0, mw, nw, lane);
    CP_WAIT(0); __syncthreads();
    mma_tile(acc, Ac, 64, w1, mw, nw, lane);

    #pragma unroll
    for (int mt = 0; mt < 2; mt++) {
        #pragma unroll
        for (int half = 0; half < 2; half++) {
            const int r = row0 + mw * 32 + mt * 16 + (lane >> 2) + half * 8;
            if (r < EE) {
                #pragma unroll
                for (int j = 0; j < 4; j++) {
                    const int col = nw * 32 + j * 8 + 2 * (lane & 3);
                    const size_t yb = (size_t)r * 128 + col;
                    float2 o;
                    o.x = acc[mt][j][half * 2 + 0] + bias[col] + resid[yb];
                    o.y = acc[mt][j][half * 2 + 1] + bias[col + 1] + resid[yb + 1];
                    *reinterpret_cast<float2 *>(Y + yb) = o;
                }
            }
        }
    }
}

// --------------- single-launch weight convert/transpose --------------------
struct WDesc { const float *W; int K; int No; int ofs; int start; };
struct WPack { WDesc d[10]; int total; };

__global__ void split_all(WPack p, __half *__restrict__ out)
{
    int i = blockIdx.x * 256 + threadIdx.x;
    if (i >= p.total) return;
    #pragma unroll
    for (int m = 0; m < 10; m++) {
        const WDesc &d = p.d[m];
        const int sz = d.K * d.No;
        if (i < d.start + sz) {
            const int il = i - d.start;
            const int k = il / d.No;
            const int n = il - k * d.No;
            out[(size_t)d.ofs + (size_t)n * d.K + k] = __float2half(d.W[il]);
            return;
        }
    }
}

__global__ void pack_bias(const float *__restrict__ a, const float *__restrict__ b,
                          const float *__restrict__ c, float *__restrict__ o)
{
    const int i = threadIdx.x;
    if (i < 128) { o[i] = a[i]; o[128 + i] = b[i]; o[256 + i] = c[i]; }
}

// ---------------------------------------------------------------------------
extern "C" void kernel_launch(void *const *d_in, const int *in_sizes, int n_in,
                              void *d_out, int out_size)
{
    const float *node   = (const float *)d_in[0];
    const float *edge   = (const float *)d_in[1];
    const int   *src    = (const int *)d_in[2];
    const int   *dst    = (const int *)d_in[3];
    const float *ln1n_w = (const float *)d_in[4];
    const float *ln1n_b = (const float *)d_in[5];
    const float *ln1e_w = (const float *)d_in[6];
    const float *ln1e_b = (const float *)d_in[7];
    const float *ln2n_w = (const float *)d_in[8];
    const float *ln2n_b = (const float *)d_in[9];
    const float *ln2e_w = (const float *)d_in[10];
    const float *ln2e_b = (const float *)d_in[11];
    const float *Wq = (const float *)d_in[12];  const float *bq = (const float *)d_in[13];
    const float *Wk = (const float *)d_in[14];  const float *bk = (const float *)d_in[15];
    const float *Wv = (const float *)d_in[16];  const float *bv = (const float *)d_in[17];
    const float *We = (const float *)d_in[18];  const float *be = (const float *)d_in[19];
    const float *Wo_n = (const float *)d_in[20]; const float *bo_n = (const float *)d_in[21];
    const float *Wo_e = (const float *)d_in[22]; const float *bo_e = (const float *)d_in[23];
    const float *w1n = (const float *)d_in[24];
    const float *w2n = (const float *)d_in[25];
    const float *w1e = (const float *)d_in[26];
    const float *w2e = (const float *)d_in[27];

    float *outh = (float *)d_out;
    float *oute = outh + (size_t)NN * DD;

    float *QKVp, *Pp, *wVp, *zp, *bqkv;
    __half *WFp;
    cudaGetSymbolAddress((void **)&QKVp, g_QKV);
    cudaGetSymbolAddress((void **)&Pp,  g_P);
    cudaGetSymbolAddress((void **)&wVp, g_wV);
    cudaGetSymbolAddress((void **)&zp,  g_z);
    cudaGetSymbolAddress((void **)&bqkv, g_bqkv);
    cudaGetSymbolAddress((void **)&WFp, g_WF);

    cudaFuncSetAttribute(tcgemm,    cudaFuncAttributeMaxDynamicSharedMemorySize, G_TOT);
    cudaFuncSetAttribute(mlp_chain, cudaFuncAttributeMaxDynamicSharedMemorySize, C_TOT);
    cudaFuncSetAttribute(attn_gemm, cudaFuncAttributeMaxDynamicSharedMemorySize, T_TOT);

    // single-launch weight convert (keeps prologue short so ncu -s 5 hits GEMMs)
    WPack p;
    int st = 0;
    auto add = [&](int m, const float *W, int K, int No, int ofs) {
        p.d[m] = {W, K, No, ofs, st};
        st += K * No;
    };
    add(0, Wq, 128, 128, OF_QKV);
    add(1, Wk, 128, 128, OF_QKV + 16384);
    add(2, Wv, 128, 128, OF_QKV + 32768);
    add(3, We, 128, 128, OF_WE);
    add(4, Wo_n, 128, 128, OF_WON);
    add(5, Wo_e, 128, 128, OF_WOE);
    add(6, w1n, 128, 256, OF_W1N);
    add(7, w2n, 256, 128, OF_W2N);
    add(8, w1e, 128, 256, OF_W1E);
    add(9, w2e, 256, 128, OF_W2E);
    p.total = st;
    split_all<<<(st + 255) / 256, 256>>>(p, WFp);
    pack_bias<<<1, 128>>>(bq, bk, bv, bqkv);

    cudaMemsetAsync(wVp, 0, (size_t)NN * DD * sizeof(float), 0);
    cudaMemsetAsync(zp,  0, (size_t)NN * HH * sizeof(float), 0);

    const int GN = (NN + 63) / 64;
    const int GE = (EE + 63) / 64;

    // LN1 + fused QKV projection (No=384); LN1 + edge projection -> P
    tcgemm<<<GN, 256, G_TOT>>>(node, 128, ln1n_w, ln1n_b, nullptr,
                               WFp + OF_QKV, 384, bqkv, nullptr,
                               QKVp, 384, NN);
    tcgemm<<<GE, 256, G_TOT>>>(edge, 128, ln1e_w, ln1e_b, nullptr,
                               WFp + OF_WE, 128, be, nullptr,
                               Pp, 128, EE);

    // fused edge attention + Wo_e + resid -> oute (also scatters wV, z)
    attn_gemm<<<GE, 256, T_TOT>>>(Pp, QKVp, src, dst,
                                  WFp + OF_WOE, bo_e, edge,
                                  wVp, zp, oute);

    // node output projection: A = wV / z, + resid -> outh
    tcgemm<<<GN, 256, G_TOT>>>(wVp, 128, nullptr, nullptr, zp,
                               WFp + OF_WON, 128, bo_n, node,
                               outh, 128, NN);

    // fused LN2 + MLP + resid, in place
    mlp_chain<<<GN, 256, C_TOT>>>(outh, ln2n_w, ln2n_b,
                                  WFp + OF_W1N, WFp + OF_W2N, NN);
    mlp_chain<<<GE, 256, C_TOT>>>(oute, ln2e_w, ln2e_b,
                                  WFp + OF_W1E, WFp + OF_W2E, EE);
}